// round 5
// baseline (speedup 1.0000x reference)
#include <cuda_runtime.h>

#define NN 50000
#define NE 800000
#define INDIM 64
#define HID 128
#define NL 4
#define NG 128
#define BN_EPS 1e-5f

// ---------------- scratch (device globals; no allocation allowed) ----------------
__device__ float  g_h[NN * HID];      // node features
__device__ float  g_aggr[NN * HID];   // h + edge aggregation / reused as z
__device__ float  g_z1[NN * HID];     // hidden of conv MLP
__device__ float  g_vn[NG * HID];
__device__ float  g_vnup[NG * HID];
__device__ double g_bn_sum[HID];
__device__ double g_bn_sqs[HID];
__device__ float  g_scale[HID];
__device__ float  g_shift[HID];
__device__ int    g_deg[NN];
__device__ int    g_rowptr[NN + 1];
__device__ int    g_cursor[NN];
__device__ int    g_srcs[NE];         // src node id, CSR-ordered by dst
__device__ float2 g_ea2[NE];          // edge_attr, CSR-ordered by dst
__device__ int    g_cnt[NG];
__device__ int    g_goff[NG + 1];

// ---------------- packed f32x2 helpers (Blackwell FFMA2) ----------------
#define PACK2(U, X, Y)  asm("mov.b64 %0, {%1, %2};" : "=l"(U) : "f"(X), "f"(Y))
#define PACKB(U, X)     asm("mov.b64 %0, {%1, %1};" : "=l"(U) : "f"(X))
#define UNPK2(X, Y, U)  asm("mov.b64 {%0, %1}, %2;" : "=f"(X), "=f"(Y) : "l"(U))
#define FMA2(ACC, A, B) asm("fma.rn.f32x2 %0, %1, %2, %0;" : "+l"(ACC) : "l"(A), "l"(B))

// ---------------- small utility kernels ----------------
__global__ void k_zero0() {
    int i = blockIdx.x * blockDim.x + threadIdx.x;
    if (i < NN) g_deg[i] = 0;
    if (i < NG * HID) g_vn[i] = 0.f;
    if (i < NG) g_cnt[i] = 0;
}

__global__ void k_deg(const int* __restrict__ dst) {
    int j = blockIdx.x * blockDim.x + threadIdx.x;
    if (j < NE) atomicAdd(&g_deg[dst[j]], 1);
}

// single-block full scan of degrees -> rowptr + cursor
__global__ __launch_bounds__(1024) void k_scanall() {
    __shared__ int s[1024];
    int t = threadIdx.x;
    const int CH = (NN + 1023) / 1024;   // 49
    int base = t * CH;
    int sum = 0;
    for (int j = 0; j < CH; j++) {
        int i = base + j;
        if (i < NN) sum += g_deg[i];
    }
    s[t] = sum;
    __syncthreads();
    for (int off = 1; off < 1024; off <<= 1) {
        int v = (t >= off) ? s[t - off] : 0;
        __syncthreads();
        s[t] += v;
        __syncthreads();
    }
    int pref = (t == 0) ? 0 : s[t - 1];
    for (int j = 0; j < CH; j++) {
        int i = base + j;
        if (i < NN) {
            int d = g_deg[i];
            g_cursor[i] = pref;          // rowptr[i]
            pref += d;
            g_rowptr[i + 1] = pref;
        }
    }
    if (t == 0) g_rowptr[0] = 0;
}

// fill CSR, pre-gathering src ids and edge attrs into CSR order
__global__ void k_fill(const int* __restrict__ dst, const int* __restrict__ src,
                       const float* __restrict__ ea) {
    int j = blockIdx.x * blockDim.x + threadIdx.x;
    if (j < NE) {
        int d = dst[j];
        int pos = atomicAdd(&g_cursor[d], 1);
        g_srcs[pos] = src[j];
        g_ea2[pos]  = ((const float2*)ea)[j];
    }
}

__global__ void k_cnt(const int* __restrict__ batch) {
    __shared__ int hist[NG];
    int t = threadIdx.x;
    if (t < NG) hist[t] = 0;
    __syncthreads();
    for (int i = blockIdx.x * blockDim.x + t; i < NN; i += gridDim.x * blockDim.x)
        atomicAdd(&hist[batch[i]], 1);
    __syncthreads();
    if (t < NG) atomicAdd(&g_cnt[t], hist[t]);
}

// scan of graph counts -> g_goff; also zero BN stats for first layer
__global__ __launch_bounds__(NG) void k_goff() {
    __shared__ int s[NG];
    int t = threadIdx.x;
    s[t] = g_cnt[t];
    __syncthreads();
    for (int off = 1; off < NG; off <<= 1) {
        int v = (t >= off) ? s[t - off] : 0;
        __syncthreads();
        s[t] += v;
        __syncthreads();
    }
    g_goff[t + 1] = s[t];
    if (t == 0) g_goff[0] = 0;
    g_bn_sum[t] = 0.0;
    g_bn_sqs[t] = 0.0;
}

// ---------------- input GEMM: h = x @ W_in + b_in  (K=64) ----------------
#define GR 64
#define GT 256

__global__ __launch_bounds__(GT) void k_gemm_in(const float* __restrict__ x,
                                                const float* __restrict__ W,
                                                const float* __restrict__ B) {
    __shared__ float Ws[INDIM * HID];   // 32 KB
    __shared__ float As[GR * INDIM];    // 16 KB
    int t = threadIdx.x;
    int tx = t & 31, ty = t >> 5;
    int row0 = blockIdx.x * GR;

    for (int i = t; i < INDIM * HID / 4; i += GT)
        ((float4*)Ws)[i] = ((const float4*)W)[i];
    for (int i = t; i < GR * INDIM / 4; i += GT) {
        int r = i >> 4, kc = i & 15;
        int gr = row0 + r;
        ((float4*)As)[i] = (gr < NN) ? ((const float4*)x)[gr * (INDIM / 4) + kc]
                                     : make_float4(0.f, 0.f, 0.f, 0.f);
    }
    __syncthreads();

    unsigned long long a01[8], a23[8];
#pragma unroll
    for (int i = 0; i < 8; i++) { a01[i] = 0ull; a23[i] = 0ull; }
    int r0 = ty * 8;

#pragma unroll 4
    for (int k = 0; k < INDIM; k++) {
        float4 w = ((float4*)Ws)[k * 32 + tx];
        unsigned long long w01, w23;
        PACK2(w01, w.x, w.y);
        PACK2(w23, w.z, w.w);
#pragma unroll
        for (int i = 0; i < 8; i++) {
            float a = As[(r0 + i) * INDIM + k];
            unsigned long long ap;
            PACKB(ap, a);
            FMA2(a01[i], ap, w01);
            FMA2(a23[i], ap, w23);
        }
    }
    float4 bb = ((const float4*)B)[tx];
#pragma unroll
    for (int i = 0; i < 8; i++) {
        int gr = row0 + r0 + i;
        if (gr < NN) {
            float4 o;
            UNPK2(o.x, o.y, a01[i]);
            UNPK2(o.z, o.w, a23[i]);
            o.x += bb.x; o.y += bb.y; o.z += bb.z; o.w += bb.w;
            ((float4*)g_h)[gr * 32 + tx] = o;
        }
    }
}

// ---------------- main 128x128 GEMMs ----------------
// MODE 0: z1 = relu(aggr @ W1 + b1)          (aggr already holds h + messages)
// MODE 1: z  = z1 @ W2 + b2 (into g_aggr) + column sum/sumsq stats (double)
#define SMEM_SZ ((HID * HID + GR * HID) * 4)

template <int MODE>
__global__ __launch_bounds__(GT) void k_gemm128(const float* __restrict__ W,
                                                const float* __restrict__ B) {
    extern __shared__ float sm[];
    float* Ws = sm;                // 64 KB
    float* As = sm + HID * HID;    // 32 KB
    int t = threadIdx.x;
    int tx = t & 31, ty = t >> 5;
    int row0 = blockIdx.x * GR;

    for (int i = t; i < HID * HID / 4; i += GT)
        ((float4*)Ws)[i] = ((const float4*)W)[i];
    for (int i = t; i < GR * HID / 4; i += GT) {
        int r = i >> 5, kc = i & 31;
        int gr = row0 + r;
        float4 v = make_float4(0.f, 0.f, 0.f, 0.f);
        if (gr < NN) {
            if (MODE == 0) v = ((const float4*)g_aggr)[gr * 32 + kc];
            else           v = ((const float4*)g_z1)[gr * 32 + kc];
        }
        ((float4*)As)[i] = v;
    }
    __syncthreads();

    unsigned long long a01[8], a23[8];
#pragma unroll
    for (int i = 0; i < 8; i++) { a01[i] = 0ull; a23[i] = 0ull; }
    int r0 = ty * 8;

#pragma unroll 4
    for (int k = 0; k < HID; k++) {
        float4 w = ((float4*)Ws)[k * 32 + tx];
        unsigned long long w01, w23;
        PACK2(w01, w.x, w.y);
        PACK2(w23, w.z, w.w);
#pragma unroll
        for (int i = 0; i < 8; i++) {
            float a = As[(r0 + i) * HID + k];
            unsigned long long ap;
            PACKB(ap, a);
            FMA2(a01[i], ap, w01);
            FMA2(a23[i], ap, w23);
        }
    }

    float4 bb = ((const float4*)B)[tx];

    if (MODE == 0) {
#pragma unroll
        for (int i = 0; i < 8; i++) {
            int gr = row0 + r0 + i;
            if (gr < NN) {
                float4 o;
                UNPK2(o.x, o.y, a01[i]);
                UNPK2(o.z, o.w, a23[i]);
                o.x = fmaxf(o.x + bb.x, 0.f); o.y = fmaxf(o.y + bb.y, 0.f);
                o.z = fmaxf(o.z + bb.z, 0.f); o.w = fmaxf(o.w + bb.w, 0.f);
                ((float4*)g_z1)[gr * 32 + tx] = o;
            }
        }
    } else {
        double ls[4] = {0, 0, 0, 0}, lq[4] = {0, 0, 0, 0};
#pragma unroll
        for (int i = 0; i < 8; i++) {
            int gr = row0 + r0 + i;
            if (gr < NN) {
                float4 o;
                UNPK2(o.x, o.y, a01[i]);
                UNPK2(o.z, o.w, a23[i]);
                o.x += bb.x; o.y += bb.y; o.z += bb.z; o.w += bb.w;
                ((float4*)g_aggr)[gr * 32 + tx] = o;
                double d0 = (double)o.x, d1 = (double)o.y;
                double d2 = (double)o.z, d3 = (double)o.w;
                ls[0] += d0; lq[0] += d0 * d0;
                ls[1] += d1; lq[1] += d1 * d1;
                ls[2] += d2; lq[2] += d2 * d2;
                ls[3] += d3; lq[3] += d3 * d3;
            }
        }
        __syncthreads();                     // done reading As, reuse as stats
        double* ssum = (double*)As;          // 128 doubles
        double* ssq  = ssum + HID;           // 128 doubles
        if (t < HID) { ssum[t] = 0.0; ssq[t] = 0.0; }
        __syncthreads();
#pragma unroll
        for (int j = 0; j < 4; j++) {
            atomicAdd(&ssum[tx * 4 + j], ls[j]);
            atomicAdd(&ssq[tx * 4 + j], lq[j]);
        }
        __syncthreads();
        if (t < HID) {
            atomicAdd(&g_bn_sum[t], ssum[t]);
            atomicAdd(&g_bn_sqs[t], ssq[t]);
        }
    }
}

// ---------------- virtual node broadcast: h += vn[batch] ----------------
__global__ void k_addvn(const int* __restrict__ batch) {
    int idx = blockIdx.x * blockDim.x + threadIdx.x;   // over NN*32 float4s
    if (idx >= NN * 32) return;
    int n = idx >> 5, c4 = idx & 31;
    int g = batch[n];
    float4 v = ((const float4*)g_vn)[g * 32 + c4];
    float4 h = ((float4*)g_h)[idx];
    h.x += v.x; h.y += v.y; h.z += v.z; h.w += v.w;
    ((float4*)g_h)[idx] = h;
}

// ---------------- CSR gather: aggr[n] = h[n] + sum_e relu(h[src] + e_vec) ----------
#define GA_LOAD(P, HV, AV)                                        \
    do {                                                          \
        int _sn = g_srcs[P];                                      \
        AV = g_ea2[P];                                            \
        HV = ((const float4*)g_h)[_sn * 32 + lane];               \
    } while (0)

#define GA_FMA(HV, AV)                                                          \
    do {                                                                        \
        acc.x += fmaxf(HV.x + fmaf(AV.x, w0.x, fmaf(AV.y, w1.x, b4.x)), 0.f);   \
        acc.y += fmaxf(HV.y + fmaf(AV.x, w0.y, fmaf(AV.y, w1.y, b4.y)), 0.f);   \
        acc.z += fmaxf(HV.z + fmaf(AV.x, w0.z, fmaf(AV.y, w1.z, b4.z)), 0.f);   \
        acc.w += fmaxf(HV.w + fmaf(AV.x, w0.w, fmaf(AV.y, w1.w, b4.w)), 0.f);   \
    } while (0)

__global__ __launch_bounds__(256) void k_gather(const float* __restrict__ We,
                                                const float* __restrict__ be) {
    int n = (blockIdx.x * blockDim.x + threadIdx.x) >> 5;
    int lane = threadIdx.x & 31;
    if (n >= NN) return;
    float4 acc = ((const float4*)g_h)[n * 32 + lane];   // z = h + aggr fused
    float4 w0 = ((const float4*)We)[lane];              // row 0 of W_e
    float4 w1 = ((const float4*)We)[32 + lane];         // row 1 of W_e
    float4 b4 = ((const float4*)be)[lane];
    int p = g_rowptr[n], e = g_rowptr[n + 1];

    float4 h0, h1, h2, h3;
    float2 a0, a1, a2, a3;
    if (p + 0 < e) GA_LOAD(p + 0, h0, a0);
    if (p + 1 < e) GA_LOAD(p + 1, h1, a1);
    if (p + 2 < e) GA_LOAD(p + 2, h2, a2);
    if (p + 3 < e) GA_LOAD(p + 3, h3, a3);

    while (p + 4 <= e) {
        GA_FMA(h0, a0); GA_FMA(h1, a1); GA_FMA(h2, a2); GA_FMA(h3, a3);
        p += 4;
        if (p + 0 < e) GA_LOAD(p + 0, h0, a0);
        if (p + 1 < e) GA_LOAD(p + 1, h1, a1);
        if (p + 2 < e) GA_LOAD(p + 2, h2, a2);
        if (p + 3 < e) GA_LOAD(p + 3, h3, a3);
    }
    int r = e - p;
    if (r > 0) GA_FMA(h0, a0);
    if (r > 1) GA_FMA(h1, a1);
    if (r > 2) GA_FMA(h2, a2);

    ((float4*)g_aggr)[n * 32 + lane] = acc;
}

// ---------------- BN finalize: stats -> scale/shift; re-zero stats ----------------
__global__ __launch_bounds__(HID) void k_bnfin(const float* __restrict__ bng,
                                               const float* __restrict__ bnb) {
    int c = threadIdx.x;
    double mu = g_bn_sum[c] / (double)NN;
    double var = g_bn_sqs[c] / (double)NN - mu * mu;
    if (var < 0.0) var = 0.0;
    float scale = bng[c] * rsqrtf((float)var + BN_EPS);
    g_scale[c] = scale;
    g_shift[c] = bnb[c] - (float)mu * scale;
    g_bn_sum[c] = 0.0;
    g_bn_sqs[c] = 0.0;
}

// ---------------- fused BN apply + relu + per-graph pool (no atomics) -------------
// One block per graph (batch sorted => contiguous node range [goff[g], goff[g+1])).
__global__ __launch_bounds__(HID) void k_bnpool() {
    int g = blockIdx.x, c = threadIdx.x;
    float scale = g_scale[c], shift = g_shift[c];
    int n = g_goff[g], e = g_goff[g + 1];
    float acc = 0.f;
    for (; n < e; n++) {
        float z = g_aggr[n * HID + c];
        float v = fmaxf(fmaf(z, scale, shift), 0.f);
        g_h[n * HID + c] = v;
        acc += v;
    }
    g_vnup[g * HID + c] = acc;
}

// ---------------- virtual node MLP: vn += mlp(vnup) ----------------
__global__ __launch_bounds__(HID) void k_vnmlp(const float* __restrict__ W1,
                                               const float* __restrict__ b1,
                                               const float* __restrict__ W2,
                                               const float* __restrict__ b2) {
    int g = blockIdx.x, c = threadIdx.x;
    __shared__ float u[HID], tt[HID];
    u[c] = g_vnup[g * HID + c];
    __syncthreads();
    float a = b1[c];
#pragma unroll 4
    for (int k = 0; k < HID; k++) a = fmaf(u[k], W1[k * HID + c], a);
    tt[c] = fmaxf(a, 0.f);
    __syncthreads();
    float o = b2[c];
#pragma unroll 4
    for (int k = 0; k < HID; k++) o = fmaf(tt[k], W2[k * HID + c], o);
    g_vn[g * HID + c] += o;
}

// ---------------- classifier ----------------
__global__ __launch_bounds__(HID) void k_cls(const float* __restrict__ W1,
                                             const float* __restrict__ b1,
                                             const float* __restrict__ W2,
                                             const float* __restrict__ b2,
                                             float* __restrict__ out) {
    int g = blockIdx.x, c = threadIdx.x;
    __shared__ float u[HID], tt[HID], red[HID];
    float cnt = fmaxf((float)g_cnt[g], 1.f);
    u[c] = g_vnup[g * HID + c] / cnt;
    __syncthreads();
    float a = b1[c];
#pragma unroll 4
    for (int k = 0; k < HID; k++) a = fmaf(u[k], W1[k * HID + c], a);
    tt[c] = fmaxf(a, 0.f);
    __syncthreads();
    red[c] = tt[c] * W2[c];
    __syncthreads();
    for (int s = 64; s > 0; s >>= 1) {
        if (c < s) red[c] += red[c + s];
        __syncthreads();
    }
    if (c == 0) out[g] = red[0] + b2[0];
}

// ---------------- host ----------------
extern "C" void kernel_launch(void* const* d_in, const int* in_sizes, int n_in,
                              void* d_out, int out_size) {
    const float *x, *ea, *W_in, *b_in, *W_e, *b_e, *cW1, *cb1, *cW2, *cb2;
    const float *bng, *bnb, *vW1, *vb1, *vW2, *vb2, *clW1, *clb1, *clW2, *clb2;
    const int *ei, *batch;

    if (in_sizes[2] == 2 * NE) {
        // setup_inputs dict order
        x    = (const float*)d_in[0];  ea   = (const float*)d_in[1];
        ei   = (const int*)d_in[2];    batch= (const int*)d_in[3];
        W_in = (const float*)d_in[4];  b_in = (const float*)d_in[5];
        W_e  = (const float*)d_in[6];  b_e  = (const float*)d_in[7];
        cW1  = (const float*)d_in[8];  cb1  = (const float*)d_in[9];
        cW2  = (const float*)d_in[10]; cb2  = (const float*)d_in[11];
        bng  = (const float*)d_in[12]; bnb  = (const float*)d_in[13];
        vW1  = (const float*)d_in[14]; vb1  = (const float*)d_in[15];
        vW2  = (const float*)d_in[16]; vb2  = (const float*)d_in[17];
        clW1 = (const float*)d_in[18]; clb1 = (const float*)d_in[19];
        clW2 = (const float*)d_in[20]; clb2 = (const float*)d_in[21];
    } else {
        // reference() argument order
        x    = (const float*)d_in[0];  ea   = (const float*)d_in[1];
        W_in = (const float*)d_in[2];  b_in = (const float*)d_in[3];
        W_e  = (const float*)d_in[4];  b_e  = (const float*)d_in[5];
        cW1  = (const float*)d_in[6];  cb1  = (const float*)d_in[7];
        cW2  = (const float*)d_in[8];  cb2  = (const float*)d_in[9];
        bng  = (const float*)d_in[10]; bnb  = (const float*)d_in[11];
        vW1  = (const float*)d_in[12]; vb1  = (const float*)d_in[13];
        vW2  = (const float*)d_in[14]; vb2  = (const float*)d_in[15];
        clW1 = (const float*)d_in[16]; clb1 = (const float*)d_in[17];
        clW2 = (const float*)d_in[18]; clb2 = (const float*)d_in[19];
        ei   = (const int*)d_in[20];   batch= (const int*)d_in[21];
    }
    const int* src = ei;
    const int* dst = ei + NE;

    cudaFuncSetAttribute(k_gemm128<0>, cudaFuncAttributeMaxDynamicSharedMemorySize, SMEM_SZ);
    cudaFuncSetAttribute(k_gemm128<1>, cudaFuncAttributeMaxDynamicSharedMemorySize, SMEM_SZ);

    // CSR build + init. Launch order puts k_gather at index 5 (ncu -s 5 -c 1).
    k_zero0<<<(NN + 255) / 256, 256>>>();                       // 0
    k_deg<<<(NE + 255) / 256, 256>>>(dst);                      // 1
    k_scanall<<<1, 1024>>>();                                   // 2
    k_fill<<<(NE + 255) / 256, 256>>>(dst, src, ea);            // 3
    k_gemm_in<<<(NN + GR - 1) / GR, GT>>>(x, W_in, b_in);       // 4
    k_gather<<<(NN * 32 + 255) / 256, 256>>>(W_e, b_e);         // 5 <- profiled
    k_cnt<<<64, 256>>>(batch);                                  // 6
    k_goff<<<1, NG>>>();                                        // 7 (also zeroes BN stats)

    for (int i = 0; i < NL; i++) {
        if (i > 0) {
            k_addvn<<<(NN * 32 + 255) / 256, 256>>>(batch);
            k_gather<<<(NN * 32 + 255) / 256, 256>>>(W_e, b_e);
        }
        k_gemm128<0><<<(NN + GR - 1) / GR, GT, SMEM_SZ>>>(cW1 + i * HID * HID, cb1 + i * HID);
        k_gemm128<1><<<(NN + GR - 1) / GR, GT, SMEM_SZ>>>(cW2 + i * HID * HID, cb2 + i * HID);
        k_bnfin<<<1, HID>>>(bng + i * HID, bnb + i * HID);
        k_bnpool<<<NG, HID>>>();
        if (i < NL - 1) k_vnmlp<<<NG, HID>>>(vW1, vb1, vW2, vb2);
    }
    k_cls<<<NG, HID>>>(clW1, clb1, clW2, clb2, (float*)d_out);
}

// round 16
// speedup vs baseline: 1.3692x; 1.3692x over previous
#include <cuda_runtime.h>

#define NN 50000
#define NE 800000
#define INDIM 64
#define HID 128
#define NL 4
#define NG 128
#define BN_EPS 1e-5f

// ---------------- scratch (device globals; no allocation allowed) ----------------
__device__ float  g_h[NN * HID];      // node features
__device__ float  g_aggr[NN * HID];   // h + edge aggregation / reused as z
__device__ float  g_z1[NN * HID];     // hidden of conv MLP
__device__ float  g_vn[NG * HID];
__device__ float  g_vnup[NG * HID];
__device__ double g_bn_sum[HID];
__device__ double g_bn_sqs[HID];
__device__ float  g_scale[HID];
__device__ float  g_shift[HID];
__device__ int    g_deg[NN];
__device__ int    g_rowptr[NN + 1];
__device__ int    g_cursor[NN];
__device__ int    g_srcs[NE];         // src node id, CSR-ordered by dst
__device__ float2 g_ea2[NE];          // edge_attr, CSR-ordered by dst
__device__ int    g_cnt[NG];
__device__ int    g_goff[NG + 1];

// ---------------- packed f32x2 helpers (Blackwell FFMA2) ----------------
#define PACKB(U, X)     asm("mov.b64 %0, {%1, %1};" : "=l"(U) : "f"(X))
#define UNPK2(X, Y, U)  asm("mov.b64 {%0, %1}, %2;" : "=f"(X), "=f"(Y) : "l"(U))
#define FMA2(ACC, A, B) asm("fma.rn.f32x2 %0, %1, %2, %0;" : "+l"(ACC) : "l"(A), "l"(B))

// ---------------- small utility kernels ----------------
__global__ void k_zero0() {
    int i = blockIdx.x * blockDim.x + threadIdx.x;
    if (i < NN) g_deg[i] = 0;
    if (i < NG * HID) g_vn[i] = 0.f;
    if (i < NG) g_cnt[i] = 0;
}

__global__ void k_deg(const int* __restrict__ dst) {
    int j = blockIdx.x * blockDim.x + threadIdx.x;
    if (j < NE) atomicAdd(&g_deg[dst[j]], 1);
}

// single-block full scan of degrees -> rowptr + cursor
__global__ __launch_bounds__(1024) void k_scanall() {
    __shared__ int s[1024];
    int t = threadIdx.x;
    const int CH = (NN + 1023) / 1024;   // 49
    int base = t * CH;
    int sum = 0;
    for (int j = 0; j < CH; j++) {
        int i = base + j;
        if (i < NN) sum += g_deg[i];
    }
    s[t] = sum;
    __syncthreads();
    for (int off = 1; off < 1024; off <<= 1) {
        int v = (t >= off) ? s[t - off] : 0;
        __syncthreads();
        s[t] += v;
        __syncthreads();
    }
    int pref = (t == 0) ? 0 : s[t - 1];
    for (int j = 0; j < CH; j++) {
        int i = base + j;
        if (i < NN) {
            int d = g_deg[i];
            g_cursor[i] = pref;          // rowptr[i]
            pref += d;
            g_rowptr[i + 1] = pref;
        }
    }
    if (t == 0) g_rowptr[0] = 0;
}

// fill CSR, pre-gathering src ids and edge attrs into CSR order
__global__ void k_fill(const int* __restrict__ dst, const int* __restrict__ src,
                       const float* __restrict__ ea) {
    int j = blockIdx.x * blockDim.x + threadIdx.x;
    if (j < NE) {
        int d = dst[j];
        int pos = atomicAdd(&g_cursor[d], 1);
        g_srcs[pos] = src[j];
        g_ea2[pos]  = ((const float2*)ea)[j];
    }
}

__global__ void k_cnt(const int* __restrict__ batch) {
    __shared__ int hist[NG];
    int t = threadIdx.x;
    if (t < NG) hist[t] = 0;
    __syncthreads();
    for (int i = blockIdx.x * blockDim.x + t; i < NN; i += gridDim.x * blockDim.x)
        atomicAdd(&hist[batch[i]], 1);
    __syncthreads();
    if (t < NG) atomicAdd(&g_cnt[t], hist[t]);
}

// scan of graph counts -> g_goff; also zero BN stats for first layer
__global__ __launch_bounds__(NG) void k_goff() {
    __shared__ int s[NG];
    int t = threadIdx.x;
    s[t] = g_cnt[t];
    __syncthreads();
    for (int off = 1; off < NG; off <<= 1) {
        int v = (t >= off) ? s[t - off] : 0;
        __syncthreads();
        s[t] += v;
        __syncthreads();
    }
    g_goff[t + 1] = s[t];
    if (t == 0) g_goff[0] = 0;
    g_bn_sum[t] = 0.0;
    g_bn_sqs[t] = 0.0;
}

// ---------------- GEMM tiles (row-major A tile, R3 layout; FFMA2 mainloop) --------
#define GR 64
#define GT 256

// input GEMM: h = x @ W_in + b_in  (K=64)
__global__ __launch_bounds__(GT) void k_gemm_in(const float* __restrict__ x,
                                                const float* __restrict__ W,
                                                const float* __restrict__ B) {
    __shared__ float Ws[INDIM * HID];   // 32 KB, [k][c]
    __shared__ float As[GR * INDIM];    // 16 KB, [r][k]
    int t = threadIdx.x;
    int tx = t & 31, ty = t >> 5;
    int row0 = blockIdx.x * GR;

    for (int i = t; i < INDIM * HID / 4; i += GT)
        ((float4*)Ws)[i] = ((const float4*)W)[i];
    for (int i = t; i < GR * INDIM / 4; i += GT) {
        int r = i >> 4, kc = i & 15;
        int gr = row0 + r;
        ((float4*)As)[i] = (gr < NN) ? ((const float4*)x)[gr * (INDIM / 4) + kc]
                                     : make_float4(0.f, 0.f, 0.f, 0.f);
    }
    __syncthreads();

    unsigned long long acc01[8], acc23[8];
#pragma unroll
    for (int i = 0; i < 8; i++) { acc01[i] = 0ull; acc23[i] = 0ull; }
    int r0 = ty * 8;

#pragma unroll 4
    for (int k = 0; k < INDIM; k++) {
        ulonglong2 wv = ((const ulonglong2*)Ws)[k * 32 + tx];   // (w0,w1),(w2,w3)
#pragma unroll
        for (int i = 0; i < 8; i++) {
            float a = As[(r0 + i) * INDIM + k];
            unsigned long long ap;
            PACKB(ap, a);
            FMA2(acc01[i], ap, wv.x);
            FMA2(acc23[i], ap, wv.y);
        }
    }
    float4 bb = ((const float4*)B)[tx];
#pragma unroll
    for (int i = 0; i < 8; i++) {
        int gr = row0 + r0 + i;
        if (gr < NN) {
            float4 o;
            UNPK2(o.x, o.y, acc01[i]);
            UNPK2(o.z, o.w, acc23[i]);
            o.x += bb.x; o.y += bb.y; o.z += bb.z; o.w += bb.w;
            ((float4*)g_h)[gr * 32 + tx] = o;
        }
    }
}

// main 128x128 GEMMs
// MODE 0: z1 = relu(aggr @ W1 + b1)          (aggr already holds h + messages)
// MODE 1: z  = z1 @ W2 + b2 (into g_aggr) + column sum/sumsq stats (double)
#define SMEM_SZ ((HID * HID + GR * HID) * 4)

template <int MODE>
__global__ __launch_bounds__(GT) void k_gemm128(const float* __restrict__ W,
                                                const float* __restrict__ B) {
    extern __shared__ float sm[];
    float* Ws = sm;                // 64 KB, [k][c]
    float* As = sm + HID * HID;    // 32 KB, [r][k]
    int t = threadIdx.x;
    int tx = t & 31, ty = t >> 5;
    int row0 = blockIdx.x * GR;

    for (int i = t; i < HID * HID / 4; i += GT)
        ((float4*)Ws)[i] = ((const float4*)W)[i];
    for (int i = t; i < GR * HID / 4; i += GT) {
        int r = i >> 5, kc = i & 31;
        int gr = row0 + r;
        float4 v = make_float4(0.f, 0.f, 0.f, 0.f);
        if (gr < NN) {
            if (MODE == 0) v = ((const float4*)g_aggr)[gr * 32 + kc];
            else           v = ((const float4*)g_z1)[gr * 32 + kc];
        }
        ((float4*)As)[i] = v;
    }
    __syncthreads();

    unsigned long long acc01[8], acc23[8];
#pragma unroll
    for (int i = 0; i < 8; i++) { acc01[i] = 0ull; acc23[i] = 0ull; }
    int r0 = ty * 8;

#pragma unroll 4
    for (int k = 0; k < HID; k++) {
        ulonglong2 wv = ((const ulonglong2*)Ws)[k * 32 + tx];   // (w0,w1),(w2,w3)
#pragma unroll
        for (int i = 0; i < 8; i++) {
            float a = As[(r0 + i) * HID + k];
            unsigned long long ap;
            PACKB(ap, a);
            FMA2(acc01[i], ap, wv.x);
            FMA2(acc23[i], ap, wv.y);
        }
    }

    float4 bb = ((const float4*)B)[tx];

    if (MODE == 0) {
#pragma unroll
        for (int i = 0; i < 8; i++) {
            int gr = row0 + r0 + i;
            if (gr < NN) {
                float4 o;
                UNPK2(o.x, o.y, acc01[i]);
                UNPK2(o.z, o.w, acc23[i]);
                o.x = fmaxf(o.x + bb.x, 0.f); o.y = fmaxf(o.y + bb.y, 0.f);
                o.z = fmaxf(o.z + bb.z, 0.f); o.w = fmaxf(o.w + bb.w, 0.f);
                ((float4*)g_z1)[gr * 32 + tx] = o;
            }
        }
    } else {
        double ls[4] = {0, 0, 0, 0}, lq[4] = {0, 0, 0, 0};
#pragma unroll
        for (int i = 0; i < 8; i++) {
            int gr = row0 + r0 + i;
            if (gr < NN) {
                float4 o;
                UNPK2(o.x, o.y, acc01[i]);
                UNPK2(o.z, o.w, acc23[i]);
                o.x += bb.x; o.y += bb.y; o.z += bb.z; o.w += bb.w;
                ((float4*)g_aggr)[gr * 32 + tx] = o;
                double d0 = (double)o.x, d1 = (double)o.y;
                double d2 = (double)o.z, d3 = (double)o.w;
                ls[0] += d0; lq[0] += d0 * d0;
                ls[1] += d1; lq[1] += d1 * d1;
                ls[2] += d2; lq[2] += d2 * d2;
                ls[3] += d3; lq[3] += d3 * d3;
            }
        }
        __syncthreads();                     // done reading As, reuse as stats
        double* ssum = (double*)As;          // 128 doubles
        double* ssq  = ssum + HID;           // 128 doubles
        if (t < HID) { ssum[t] = 0.0; ssq[t] = 0.0; }
        __syncthreads();
#pragma unroll
        for (int j = 0; j < 4; j++) {
            atomicAdd(&ssum[tx * 4 + j], ls[j]);
            atomicAdd(&ssq[tx * 4 + j], lq[j]);
        }
        __syncthreads();
        if (t < HID) {
            atomicAdd(&g_bn_sum[t], ssum[t]);
            atomicAdd(&g_bn_sqs[t], ssq[t]);
        }
    }
}

// ---------------- virtual node broadcast: h += vn[batch] ----------------
__global__ void k_addvn(const int* __restrict__ batch) {
    int idx = blockIdx.x * blockDim.x + threadIdx.x;   // over NN*32 float4s
    if (idx >= NN * 32) return;
    int n = idx >> 5, c4 = idx & 31;
    int g = batch[n];
    float4 v = ((const float4*)g_vn)[g * 32 + c4];
    float4 h = ((float4*)g_h)[idx];
    h.x += v.x; h.y += v.y; h.z += v.z; h.w += v.w;
    ((float4*)g_h)[idx] = h;
}

// ---------------- CSR gather: aggr[n] = h[n] + sum_e relu(h[src] + e_vec) ----------
#define GA_LOAD(P, HV, AV)                                        \
    do {                                                          \
        int _sn = g_srcs[P];                                      \
        AV = g_ea2[P];                                            \
        HV = ((const float4*)g_h)[_sn * 32 + lane];               \
    } while (0)

#define GA_FMA(HV, AV)                                                          \
    do {                                                                        \
        acc.x += fmaxf(HV.x + fmaf(AV.x, w0.x, fmaf(AV.y, w1.x, b4.x)), 0.f);   \
        acc.y += fmaxf(HV.y + fmaf(AV.x, w0.y, fmaf(AV.y, w1.y, b4.y)), 0.f);   \
        acc.z += fmaxf(HV.z + fmaf(AV.x, w0.z, fmaf(AV.y, w1.z, b4.z)), 0.f);   \
        acc.w += fmaxf(HV.w + fmaf(AV.x, w0.w, fmaf(AV.y, w1.w, b4.w)), 0.f);   \
    } while (0)

__global__ __launch_bounds__(256) void k_gather(const float* __restrict__ We,
                                                const float* __restrict__ be) {
    int n = (blockIdx.x * blockDim.x + threadIdx.x) >> 5;
    int lane = threadIdx.x & 31;
    if (n >= NN) return;
    float4 acc = ((const float4*)g_h)[n * 32 + lane];   // z = h + aggr fused
    float4 w0 = ((const float4*)We)[lane];              // row 0 of W_e
    float4 w1 = ((const float4*)We)[32 + lane];         // row 1 of W_e
    float4 b4 = ((const float4*)be)[lane];
    int p = g_rowptr[n], e = g_rowptr[n + 1];

    float4 h0, h1, h2, h3;
    float2 a0, a1, a2, a3;
    if (p + 0 < e) GA_LOAD(p + 0, h0, a0);
    if (p + 1 < e) GA_LOAD(p + 1, h1, a1);
    if (p + 2 < e) GA_LOAD(p + 2, h2, a2);
    if (p + 3 < e) GA_LOAD(p + 3, h3, a3);

    while (p + 4 <= e) {
        GA_FMA(h0, a0); GA_FMA(h1, a1); GA_FMA(h2, a2); GA_FMA(h3, a3);
        p += 4;
        if (p + 0 < e) GA_LOAD(p + 0, h0, a0);
        if (p + 1 < e) GA_LOAD(p + 1, h1, a1);
        if (p + 2 < e) GA_LOAD(p + 2, h2, a2);
        if (p + 3 < e) GA_LOAD(p + 3, h3, a3);
    }
    int r = e - p;
    if (r > 0) GA_FMA(h0, a0);
    if (r > 1) GA_FMA(h1, a1);
    if (r > 2) GA_FMA(h2, a2);

    ((float4*)g_aggr)[n * 32 + lane] = acc;
}

// ---------------- BN finalize: stats -> scale/shift; re-zero stats ----------------
__global__ __launch_bounds__(HID) void k_bnfin(const float* __restrict__ bng,
                                               const float* __restrict__ bnb) {
    int c = threadIdx.x;
    double mu = g_bn_sum[c] / (double)NN;
    double var = g_bn_sqs[c] / (double)NN - mu * mu;
    if (var < 0.0) var = 0.0;
    float scale = bng[c] * rsqrtf((float)var + BN_EPS);
    g_scale[c] = scale;
    g_shift[c] = bnb[c] - (float)mu * scale;
    g_bn_sum[c] = 0.0;
    g_bn_sqs[c] = 0.0;
}

// ---------------- BN apply + relu (pure elementwise, fully parallel) --------------
__global__ void k_bnapply() {
    int idx = blockIdx.x * blockDim.x + threadIdx.x;   // over NN*32 float4s
    if (idx >= NN * 32) return;
    int c4 = idx & 31;
    float4 z  = ((const float4*)g_aggr)[idx];
    float4 sc = ((const float4*)g_scale)[c4];
    float4 sh = ((const float4*)g_shift)[c4];
    float4 o;
    o.x = fmaxf(fmaf(z.x, sc.x, sh.x), 0.f);
    o.y = fmaxf(fmaf(z.y, sc.y, sh.y), 0.f);
    o.z = fmaxf(fmaf(z.z, sc.z, sh.z), 0.f);
    o.w = fmaxf(fmaf(z.w, sc.w, sh.w), 0.f);
    ((float4*)g_h)[idx] = o;
}

// ---------------- per-graph pool (no atomics, 512 threads/graph) ------------------
__global__ __launch_bounds__(512) void k_pool() {
    __shared__ float red[4][HID];
    int g = blockIdx.x, t = threadIdx.x;
    int rq = t >> 7, c = t & 127;
    int e = g_goff[g + 1];
    float acc = 0.f;
    for (int n = g_goff[g] + rq; n < e; n += 4) acc += g_h[n * HID + c];
    red[rq][c] = acc;
    __syncthreads();
    if (rq == 0)
        g_vnup[g * HID + c] = (red[0][c] + red[1][c]) + (red[2][c] + red[3][c]);
}

// ---------------- virtual node MLP: vn += mlp(vnup) ----------------
__global__ __launch_bounds__(HID) void k_vnmlp(const float* __restrict__ W1,
                                               const float* __restrict__ b1,
                                               const float* __restrict__ W2,
                                               const float* __restrict__ b2) {
    int g = blockIdx.x, c = threadIdx.x;
    __shared__ float u[HID], tt[HID];
    u[c] = g_vnup[g * HID + c];
    __syncthreads();
    float a = b1[c];
#pragma unroll 4
    for (int k = 0; k < HID; k++) a = fmaf(u[k], W1[k * HID + c], a);
    tt[c] = fmaxf(a, 0.f);
    __syncthreads();
    float o = b2[c];
#pragma unroll 4
    for (int k = 0; k < HID; k++) o = fmaf(tt[k], W2[k * HID + c], o);
    g_vn[g * HID + c] += o;
}

// ---------------- classifier ----------------
__global__ __launch_bounds__(HID) void k_cls(const float* __restrict__ W1,
                                             const float* __restrict__ b1,
                                             const float* __restrict__ W2,
                                             const float* __restrict__ b2,
                                             float* __restrict__ out) {
    int g = blockIdx.x, c = threadIdx.x;
    __shared__ float u[HID], tt[HID], red[HID];
    float cnt = fmaxf((float)g_cnt[g], 1.f);
    u[c] = g_vnup[g * HID + c] / cnt;
    __syncthreads();
    float a = b1[c];
#pragma unroll 4
    for (int k = 0; k < HID; k++) a = fmaf(u[k], W1[k * HID + c], a);
    tt[c] = fmaxf(a, 0.f);
    __syncthreads();
    red[c] = tt[c] * W2[c];
    __syncthreads();
    for (int s = 64; s > 0; s >>= 1) {
        if (c < s) red[c] += red[c + s];
        __syncthreads();
    }
    if (c == 0) out[g] = red[0] + b2[0];
}

// ---------------- host ----------------
extern "C" void kernel_launch(void* const* d_in, const int* in_sizes, int n_in,
                              void* d_out, int out_size) {
    const float *x, *ea, *W_in, *b_in, *W_e, *b_e, *cW1, *cb1, *cW2, *cb2;
    const float *bng, *bnb, *vW1, *vb1, *vW2, *vb2, *clW1, *clb1, *clW2, *clb2;
    const int *ei, *batch;

    if (in_sizes[2] == 2 * NE) {
        // setup_inputs dict order
        x    = (const float*)d_in[0];  ea   = (const float*)d_in[1];
        ei   = (const int*)d_in[2];    batch= (const int*)d_in[3];
        W_in = (const float*)d_in[4];  b_in = (const float*)d_in[5];
        W_e  = (const float*)d_in[6];  b_e  = (const float*)d_in[7];
        cW1  = (const float*)d_in[8];  cb1  = (const float*)d_in[9];
        cW2  = (const float*)d_in[10]; cb2  = (const float*)d_in[11];
        bng  = (const float*)d_in[12]; bnb  = (const float*)d_in[13];
        vW1  = (const float*)d_in[14]; vb1  = (const float*)d_in[15];
        vW2  = (const float*)d_in[16]; vb2  = (const float*)d_in[17];
        clW1 = (const float*)d_in[18]; clb1 = (const float*)d_in[19];
        clW2 = (const float*)d_in[20]; clb2 = (const float*)d_in[21];
    } else {
        // reference() argument order
        x    = (const float*)d_in[0];  ea   = (const float*)d_in[1];
        W_in = (const float*)d_in[2];  b_in = (const float*)d_in[3];
        W_e  = (const float*)d_in[4];  b_e  = (const float*)d_in[5];
        cW1  = (const float*)d_in[6];  cb1  = (const float*)d_in[7];
        cW2  = (const float*)d_in[8];  cb2  = (const float*)d_in[9];
        bng  = (const float*)d_in[10]; bnb  = (const float*)d_in[11];
        vW1  = (const float*)d_in[12]; vb1  = (const float*)d_in[13];
        vW2  = (const float*)d_in[14]; vb2  = (const float*)d_in[15];
        clW1 = (const float*)d_in[16]; clb1 = (const float*)d_in[17];
        clW2 = (const float*)d_in[18]; clb2 = (const float*)d_in[19];
        ei   = (const int*)d_in[20];   batch= (const int*)d_in[21];
    }
    const int* src = ei;
    const int* dst = ei + NE;

    cudaFuncSetAttribute(k_gemm128<0>, cudaFuncAttributeMaxDynamicSharedMemorySize, SMEM_SZ);
    cudaFuncSetAttribute(k_gemm128<1>, cudaFuncAttributeMaxDynamicSharedMemorySize, SMEM_SZ);

    // CSR build + init. Launch order puts k_gather at index 5 (ncu -s 5 -c 1).
    k_zero0<<<(NN + 255) / 256, 256>>>();                       // 0
    k_deg<<<(NE + 255) / 256, 256>>>(dst);                      // 1
    k_scanall<<<1, 1024>>>();                                   // 2
    k_fill<<<(NE + 255) / 256, 256>>>(dst, src, ea);            // 3
    k_gemm_in<<<(NN + GR - 1) / GR, GT>>>(x, W_in, b_in);       // 4
    k_gather<<<(NN * 32 + 255) / 256, 256>>>(W_e, b_e);         // 5 <- profiled
    k_cnt<<<64, 256>>>(batch);                                  // 6
    k_goff<<<1, NG>>>();                                        // 7 (also zeroes BN stats)

    for (int i = 0; i < NL; i++) {
        if (i > 0) {
            k_addvn<<<(NN * 32 + 255) / 256, 256>>>(batch);
            k_gather<<<(NN * 32 + 255) / 256, 256>>>(W_e, b_e);
        }
        k_gemm128<0><<<(NN + GR - 1) / GR, GT, SMEM_SZ>>>(cW1 + i * HID * HID, cb1 + i * HID);
        k_gemm128<1><<<(NN + GR - 1) / GR, GT, SMEM_SZ>>>(cW2 + i * HID * HID, cb2 + i * HID);
        k_bnfin<<<1, HID>>>(bng + i * HID, bnb + i * HID);
        k_bnapply<<<(NN * 32 + 255) / 256, 256>>>();
        k_pool<<<NG, 512>>>();
        if (i < NL - 1) k_vnmlp<<<NG, HID>>>(vW1, vb1, vW2, vb2);
    }
    k_cls<<<NG, HID>>>(clW1, clb1, clW2, clb2, (float*)d_out);
}